// round 5
// baseline (speedup 1.0000x reference)
#include <cuda_runtime.h>
#include <cstdint>

#define NODES 100000
#define IN_F 256
#define OUT_F 256
#define OUT_STRIDE 512
#define MAX_E 3200000

// ---------------- static device scratch (no runtime allocation) -------------
__device__ int   g_idx64;
__device__ int   g_off[NODES + 1];
__device__ int   g_cursor[NODES];
__device__ uint2 g_csr[MAX_E];

// ---------------- dtype probe (int64 edge indices -> odd words all zero) ----
__global__ void detect_kernel(const int* __restrict__ a,
                              const int* __restrict__ b, int E) {
    __shared__ int nz;
    if (threadIdx.x == 0) nz = 0;
    __syncthreads();
    int K = E < 2048 ? E : 2048;
    for (int i = threadIdx.x; i < K; i += blockDim.x) {
        if ((a[2 * i + 1] | b[2 * i + 1]) != 0) nz = 1;  // benign race
    }
    __syncthreads();
    if (threadIdx.x == 0) g_idx64 = (nz == 0) ? 1 : 0;
}

// ---------------- CSR build -------------------------------------------------
__global__ void zero_off_kernel() {
    int i = blockIdx.x * blockDim.x + threadIdx.x;
    if (i <= NODES) g_off[i] = 0;
}

__global__ void hist_kernel(const int* __restrict__ dst, int E) {
    int stride = g_idx64 ? 2 : 1;
    int e = blockIdx.x * blockDim.x + threadIdx.x;
    if (e < E) {
        int d = dst[e * stride];
        if ((unsigned)d < (unsigned)NODES) atomicAdd(&g_off[d + 1], 1);
    }
}

// single-block inclusive scan over g_off[0..NODES]; seeds g_cursor[i]=start(i)
// RACE FIX: trailing __syncthreads() so tid0's read of warp_sums[31] cannot
// collide with the next chunk's warp_sums writes.
__global__ void scan_kernel() {
    const int n = NODES + 1;
    __shared__ int warp_sums[32];
    __shared__ int sh_carry;
    int tid  = threadIdx.x;
    int lane = tid & 31;
    int wid  = tid >> 5;
    if (tid == 0) sh_carry = 0;
    __syncthreads();

    const int chunks = (n + 1023) / 1024;
    for (int c = 0; c < chunks; c++) {
        int idx = c * 1024 + tid;
        int x = (idx < n) ? g_off[idx] : 0;
        int v = x;
        #pragma unroll
        for (int d = 1; d < 32; d <<= 1) {
            int t = __shfl_up_sync(0xffffffffu, v, d);
            if (lane >= d) v += t;
        }
        if (lane == 31) warp_sums[wid] = v;
        __syncthreads();                               // A
        if (wid == 0) {
            int s = warp_sums[lane];
            #pragma unroll
            for (int d = 1; d < 32; d <<= 1) {
                int t = __shfl_up_sync(0xffffffffu, s, d);
                if (lane >= d) s += t;
            }
            warp_sums[lane] = s;
        }
        __syncthreads();                               // B
        int carry = sh_carry;
        int inc = carry + (wid ? warp_sums[wid - 1] : 0) + v;
        if (idx < n) g_off[idx] = inc;
        if (idx < NODES) g_cursor[idx] = inc;
        __syncthreads();                               // C
        if (tid == 0) sh_carry = carry + warp_sums[31];
        __syncthreads();                               // D (the fix)
    }
}

__global__ void scatter_kernel(const int* __restrict__ src,
                               const int* __restrict__ dst,
                               const float* __restrict__ val, int E) {
    int stride = g_idx64 ? 2 : 1;
    int e = blockIdx.x * blockDim.x + threadIdx.x;
    if (e >= E) return;
    int d = dst[e * stride];
    if ((unsigned)d >= (unsigned)NODES) return;
    int slot = atomicAdd(&g_cursor[d], 1);
    if ((unsigned)slot < (unsigned)MAX_E)
        g_csr[slot] = make_uint2((unsigned)src[e * stride],
                                 __float_as_uint(val[e]));
}

// ---------------- GEMM: out[:, 0:256] = input @ W ---------------------------
// 128x128 tile, BK=16, 256 threads, 8x8 per-thread microtile, fp32 FFMA.
#define BM 128
#define BN 128
#define BK 16

__global__ __launch_bounds__(256)
void gemm_kernel(const float* __restrict__ A,   // [M, 256]
                 const float* __restrict__ B,   // [256, 256]
                 float* __restrict__ C,         // [M, 512], writes left half
                 int M) {
    __shared__ float As[BK][BM];   // k-major
    __shared__ float Bs[BK][BN];

    int tid = threadIdx.x;
    int tx = tid & 15;
    int ty = tid >> 4;
    int row0 = blockIdx.x * BM;
    int n0   = blockIdx.y * BN;

    float acc[8][8];
    #pragma unroll
    for (int i = 0; i < 8; i++)
        #pragma unroll
        for (int j = 0; j < 8; j++) acc[i][j] = 0.f;

    for (int k0 = 0; k0 < IN_F; k0 += BK) {
        #pragma unroll
        for (int p = 0; p < 2; p++) {
            int r = (tid >> 2) + p * 64;
            int cc = (tid & 3) * 4;
            int grow = row0 + r;
            float4 v = make_float4(0.f, 0.f, 0.f, 0.f);
            if (grow < M) v = *(const float4*)&A[(size_t)grow * IN_F + k0 + cc];
            As[cc + 0][r] = v.x;
            As[cc + 1][r] = v.y;
            As[cc + 2][r] = v.z;
            As[cc + 3][r] = v.w;
        }
        #pragma unroll
        for (int p = 0; p < 2; p++) {
            int r = (tid >> 5) + p * 8;
            int cc = (tid & 31) * 4;
            *(float4*)&Bs[r][cc] = *(const float4*)&B[(size_t)(k0 + r) * OUT_F + n0 + cc];
        }
        __syncthreads();

        #pragma unroll
        for (int kk = 0; kk < BK; kk++) {
            float4 a0 = *(const float4*)&As[kk][ty * 8];
            float4 a1 = *(const float4*)&As[kk][ty * 8 + 4];
            float4 b0 = *(const float4*)&Bs[kk][tx * 8];
            float4 b1 = *(const float4*)&Bs[kk][tx * 8 + 4];
            float af[8] = {a0.x, a0.y, a0.z, a0.w, a1.x, a1.y, a1.z, a1.w};
            float bf[8] = {b0.x, b0.y, b0.z, b0.w, b1.x, b1.y, b1.z, b1.w};
            #pragma unroll
            for (int i = 0; i < 8; i++)
                #pragma unroll
                for (int j = 0; j < 8; j++)
                    acc[i][j] += af[i] * bf[j];
        }
        __syncthreads();
    }

    #pragma unroll
    for (int i = 0; i < 8; i++) {
        int row = row0 + ty * 8 + i;
        if (row < M) {
            float4 s0 = make_float4(acc[i][0], acc[i][1], acc[i][2], acc[i][3]);
            float4 s1 = make_float4(acc[i][4], acc[i][5], acc[i][6], acc[i][7]);
            *(float4*)&C[(size_t)row * OUT_STRIDE + n0 + tx * 8]     = s0;
            *(float4*)&C[(size_t)row * OUT_STRIDE + n0 + tx * 8 + 4] = s1;
        }
    }
}

// ---------------- SpMM: out[:,256:512] = segment_sum(val * ft[src]) ---------
// ft = left half of out (row stride 128 float4). 64 threads per dst node.
__global__ __launch_bounds__(256)
void spmm_kernel(const float4* __restrict__ ft, float* __restrict__ out,
                 int Nn, int E) {
    int node = blockIdx.x * 4 + (threadIdx.x >> 6);
    int lane = threadIdx.x & 63;
    if (node >= Nn) return;

    int beg = g_off[node];
    int end = g_off[node + 1];
    if (beg < 0) beg = 0;                  // defensive: can never hang again
    if (end > E) end = E;
    if (end < beg) end = beg;

    float4 acc = make_float4(0.f, 0.f, 0.f, 0.f);
    int i = beg;
    for (; i + 4 <= end; i += 4) {
        uint2 e0 = g_csr[i + 0];
        uint2 e1 = g_csr[i + 1];
        uint2 e2 = g_csr[i + 2];
        uint2 e3 = g_csr[i + 3];
        float4 v0 = __ldg(&ft[(size_t)e0.x * 128 + lane]);
        float4 v1 = __ldg(&ft[(size_t)e1.x * 128 + lane]);
        float4 v2 = __ldg(&ft[(size_t)e2.x * 128 + lane]);
        float4 v3 = __ldg(&ft[(size_t)e3.x * 128 + lane]);
        float w0 = __uint_as_float(e0.y);
        float w1 = __uint_as_float(e1.y);
        float w2 = __uint_as_float(e2.y);
        float w3 = __uint_as_float(e3.y);
        acc.x += w0 * v0.x; acc.y += w0 * v0.y; acc.z += w0 * v0.z; acc.w += w0 * v0.w;
        acc.x += w1 * v1.x; acc.y += w1 * v1.y; acc.z += w1 * v1.z; acc.w += w1 * v1.w;
        acc.x += w2 * v2.x; acc.y += w2 * v2.y; acc.z += w2 * v2.z; acc.w += w2 * v2.w;
        acc.x += w3 * v3.x; acc.y += w3 * v3.y; acc.z += w3 * v3.z; acc.w += w3 * v3.w;
    }
    for (; i < end; i++) {
        uint2 e = g_csr[i];
        float4 v = __ldg(&ft[(size_t)e.x * 128 + lane]);
        float w = __uint_as_float(e.y);
        acc.x += w * v.x; acc.y += w * v.y; acc.z += w * v.z; acc.w += w * v.w;
    }

    ((float4*)out)[(size_t)node * 128 + 64 + lane] = acc;   // right half
}

// ---------------- launch ----------------------------------------------------
extern "C" void kernel_launch(void* const* d_in, const int* in_sizes, int n_in,
                              void* d_out, int out_size) {
    const float* input  = (const float*)d_in[0];
    const int*   esrc   = (const int*)d_in[1];
    const int*   edst   = (const int*)d_in[2];
    const float* eval_  = (const float*)d_in[3];
    const float* weight = (const float*)d_in[4];
    float* out = (float*)d_out;

    int M = out_size / OUT_STRIDE;   // 100000 (unambiguous: output rows)
    int E = in_sizes[3];             // fp32 edge_val element count (unambiguous)

    detect_kernel<<<1, 256>>>(esrc, edst, E);
    zero_off_kernel<<<(NODES + 256) / 256, 256>>>();
    hist_kernel<<<(E + 255) / 256, 256>>>(edst, E);
    scan_kernel<<<1, 1024>>>();
    scatter_kernel<<<(E + 255) / 256, 256>>>(esrc, edst, eval_, E);

    dim3 ggrid((M + BM - 1) / BM, OUT_F / BN);
    gemm_kernel<<<ggrid, 256>>>(input, weight, out, M);

    spmm_kernel<<<(M + 3) / 4, 256>>>((const float4*)out, out, M, E);
}

// round 6
// speedup vs baseline: 1.3603x; 1.3603x over previous
#include <cuda_runtime.h>
#include <cstdint>

#define NODES 100000
#define IN_F 256
#define OUT_F 256
#define OUT_STRIDE 512
#define MAX_E 3200000
#define SCAN_BLK 1024
#define MAX_SCAN_BLOCKS 128   // ceil(100000/1024)=98

// ---------------- static device scratch (no runtime allocation) -------------
__device__ int   g_idx64;
__device__ int   g_cnt[NODES];
__device__ int   g_off[NODES + 1];
__device__ int   g_cursor[NODES];
__device__ int   g_bsum[MAX_SCAN_BLOCKS];
__device__ uint2 g_csr[MAX_E];

// ---------------- dtype probe (int64 edge indices -> odd words all zero) ----
__global__ void detect_kernel(const int* __restrict__ a,
                              const int* __restrict__ b, int E) {
    __shared__ int nz;
    if (threadIdx.x == 0) nz = 0;
    __syncthreads();
    int K = E < 2048 ? E : 2048;
    for (int i = threadIdx.x; i < K; i += blockDim.x) {
        if ((a[2 * i + 1] | b[2 * i + 1]) != 0) nz = 1;  // benign race
    }
    __syncthreads();
    if (threadIdx.x == 0) g_idx64 = (nz == 0) ? 1 : 0;
}

// ---------------- CSR build -------------------------------------------------
__global__ void zero_cnt_kernel(int Nn) {
    int i = blockIdx.x * blockDim.x + threadIdx.x;
    if (i < Nn) g_cnt[i] = 0;
}

__global__ void hist_kernel(const int* __restrict__ dst, int E) {
    int stride = g_idx64 ? 2 : 1;
    int e = blockIdx.x * blockDim.x + threadIdx.x;
    if (e < E) {
        int d = dst[e * stride];
        if ((unsigned)d < (unsigned)NODES) atomicAdd(&g_cnt[d], 1);
    }
}

// s1: per-block sums of g_cnt -> g_bsum[block]
__global__ __launch_bounds__(SCAN_BLK)
void scan_reduce_kernel(int Nn) {
    __shared__ int red[32];
    int lane = threadIdx.x & 31;
    int wid  = threadIdx.x >> 5;
    int idx  = blockIdx.x * SCAN_BLK + threadIdx.x;
    int x = (idx < Nn) ? g_cnt[idx] : 0;
    #pragma unroll
    for (int d = 16; d > 0; d >>= 1) x += __shfl_down_sync(0xffffffffu, x, d);
    if (lane == 0) red[wid] = x;
    __syncthreads();
    if (wid == 0) {
        int s = red[lane];
        #pragma unroll
        for (int d = 16; d > 0; d >>= 1) s += __shfl_down_sync(0xffffffffu, s, d);
        if (lane == 0) g_bsum[blockIdx.x] = s;
    }
}

// s2: exclusive scan of g_bsum[0..nb-1] (nb <= 128), one block of 128 threads.
// Also writes g_off[Nn] = total.
__global__ void scan_tops_kernel(int nb, int Nn) {
    __shared__ int wsum[4];
    int tid  = threadIdx.x;          // 0..127
    int lane = tid & 31;
    int wid  = tid >> 5;
    int x = (tid < nb) ? g_bsum[tid] : 0;
    int v = x;
    #pragma unroll
    for (int d = 1; d < 32; d <<= 1) {
        int t = __shfl_up_sync(0xffffffffu, v, d);
        if (lane >= d) v += t;
    }
    if (lane == 31) wsum[wid] = v;
    __syncthreads();
    int base = 0;
    #pragma unroll
    for (int w = 0; w < 4; w++) if (w < wid) base += wsum[w];
    if (tid < nb) g_bsum[tid] = base + v - x;   // exclusive
    if (tid == 127) g_off[Nn] = base + v;       // grand total (warp3 inclusive end)
}

// s3: block-local exclusive scan + block base -> g_off / g_cursor
__global__ __launch_bounds__(SCAN_BLK)
void scan_apply_kernel(int Nn) {
    __shared__ int wsum[32];
    int lane = threadIdx.x & 31;
    int wid  = threadIdx.x >> 5;
    int idx  = blockIdx.x * SCAN_BLK + threadIdx.x;
    int x = (idx < Nn) ? g_cnt[idx] : 0;
    int v = x;
    #pragma unroll
    for (int d = 1; d < 32; d <<= 1) {
        int t = __shfl_up_sync(0xffffffffu, v, d);
        if (lane >= d) v += t;
    }
    if (lane == 31) wsum[wid] = v;
    __syncthreads();
    if (wid == 0) {
        int s = wsum[lane];
        #pragma unroll
        for (int d = 1; d < 32; d <<= 1) {
            int t = __shfl_up_sync(0xffffffffu, s, d);
            if (lane >= d) s += t;
        }
        wsum[lane] = s;
    }
    __syncthreads();
    int base = g_bsum[blockIdx.x] + (wid ? wsum[wid - 1] : 0);
    int excl = base + v - x;
    if (idx < Nn) { g_off[idx] = excl; g_cursor[idx] = excl; }
}

__global__ void scatter_kernel(const int* __restrict__ src,
                               const int* __restrict__ dst,
                               const float* __restrict__ val, int E) {
    int stride = g_idx64 ? 2 : 1;
    int e = blockIdx.x * blockDim.x + threadIdx.x;
    if (e >= E) return;
    int d = dst[e * stride];
    if ((unsigned)d >= (unsigned)NODES) return;
    int slot = atomicAdd(&g_cursor[d], 1);
    if ((unsigned)slot < (unsigned)MAX_E)
        g_csr[slot] = make_uint2((unsigned)src[e * stride],
                                 __float_as_uint(val[e]));
}

// ---------------- tf32 tensor-core GEMM: out[:, 0:256] = input @ W ----------
// 128x128 tile, BK=32, 8 warps (4 along m, 2 along n), warp tile 32x64,
// mma.sync.m16n8k8 tf32, fp32 accumulate.

#define AS_K 36   // padded k-stride for As[m][k] / Bs[n][k] (conflict-free frags)

__device__ __forceinline__ uint32_t f2tf32(float f) {
    uint32_t u;
    asm("cvt.rna.tf32.f32 %0, %1;" : "=r"(u) : "f"(f));
    return u;
}

__device__ __forceinline__ void mma_tf32(float& c0, float& c1, float& c2, float& c3,
                                         uint32_t a0, uint32_t a1, uint32_t a2, uint32_t a3,
                                         uint32_t b0, uint32_t b1) {
    asm volatile(
        "mma.sync.aligned.m16n8k8.row.col.f32.tf32.tf32.f32 "
        "{%0,%1,%2,%3}, {%4,%5,%6,%7}, {%8,%9}, {%0,%1,%2,%3};\n"
        : "+f"(c0), "+f"(c1), "+f"(c2), "+f"(c3)
        : "r"(a0), "r"(a1), "r"(a2), "r"(a3), "r"(b0), "r"(b1));
}

__global__ __launch_bounds__(256, 2)
void gemm_tf32_kernel(const float* __restrict__ A,   // [M, 256]
                      const float* __restrict__ W,   // [256, 256]
                      float* __restrict__ C,         // [M, 512], left half
                      int M) {
    __shared__ uint32_t As[128 * AS_K];   // [m][k]
    __shared__ uint32_t Bs[128 * AS_K];   // [n][k] (transposed)

    int tid  = threadIdx.x;
    int lane = tid & 31;
    int warp = tid >> 5;
    int wm = (warp & 3) * 32;    // warp m origin within tile
    int wn = (warp >> 2) * 64;   // warp n origin within tile
    int g = lane >> 2;           // 0..7
    int t = lane & 3;            // 0..3

    int row0 = blockIdx.x * 128;
    int n0   = blockIdx.y * 128;

    float acc[2][8][4];
    #pragma unroll
    for (int mt = 0; mt < 2; mt++)
        #pragma unroll
        for (int nt = 0; nt < 8; nt++)
            #pragma unroll
            for (int c = 0; c < 4; c++) acc[mt][nt][c] = 0.f;

    for (int k0 = 0; k0 < IN_F; k0 += 32) {
        // A tile: 128 rows x 32 k  (1024 float4, 4 per thread)
        #pragma unroll
        for (int p = 0; p < 4; p++) {
            int idx = tid + 256 * p;
            int r  = idx >> 3;        // 0..127
            int c4 = idx & 7;         // 0..7 (k/4)
            int grow = row0 + r;
            float4 v = make_float4(0.f, 0.f, 0.f, 0.f);
            if (grow < M) v = *(const float4*)&A[(size_t)grow * IN_F + k0 + c4 * 4];
            uint32_t* d = &As[r * AS_K + c4 * 4];
            d[0] = f2tf32(v.x); d[1] = f2tf32(v.y);
            d[2] = f2tf32(v.z); d[3] = f2tf32(v.w);
        }
        // B tile: 32 k rows x 128 n, transposed into Bs[n][k]
        #pragma unroll
        for (int p = 0; p < 4; p++) {
            int idx = tid + 256 * p;
            int k  = idx >> 5;        // 0..31
            int c4 = idx & 31;        // 0..31 (n/4)
            float4 v = *(const float4*)&W[(size_t)(k0 + k) * OUT_F + n0 + c4 * 4];
            Bs[(c4 * 4 + 0) * AS_K + k] = f2tf32(v.x);
            Bs[(c4 * 4 + 1) * AS_K + k] = f2tf32(v.y);
            Bs[(c4 * 4 + 2) * AS_K + k] = f2tf32(v.z);
            Bs[(c4 * 4 + 3) * AS_K + k] = f2tf32(v.w);
        }
        __syncthreads();

        #pragma unroll
        for (int ks = 0; ks < 32; ks += 8) {
            uint32_t af[2][4];
            #pragma unroll
            for (int mt = 0; mt < 2; mt++) {
                int m = wm + mt * 16 + g;
                af[mt][0] = As[m * AS_K + ks + t];
                af[mt][1] = As[(m + 8) * AS_K + ks + t];
                af[mt][2] = As[m * AS_K + ks + t + 4];
                af[mt][3] = As[(m + 8) * AS_K + ks + t + 4];
            }
            #pragma unroll
            for (int nt = 0; nt < 8; nt++) {
                int n = wn + nt * 8 + g;
                uint32_t b0 = Bs[n * AS_K + ks + t];
                uint32_t b1 = Bs[n * AS_K + ks + t + 4];
                #pragma unroll
                for (int mt = 0; mt < 2; mt++)
                    mma_tf32(acc[mt][nt][0], acc[mt][nt][1],
                             acc[mt][nt][2], acc[mt][nt][3],
                             af[mt][0], af[mt][1], af[mt][2], af[mt][3], b0, b1);
            }
        }
        __syncthreads();
    }

    // store: c0/c1 at (m, 2t), c2/c3 at (m+8, 2t)
    #pragma unroll
    for (int mt = 0; mt < 2; mt++) {
        #pragma unroll
        for (int nt = 0; nt < 8; nt++) {
            int m = row0 + wm + mt * 16 + g;
            int n = n0 + wn + nt * 8 + 2 * t;
            if (m < M)
                *(float2*)&C[(size_t)m * OUT_STRIDE + n] =
                    make_float2(acc[mt][nt][0], acc[mt][nt][1]);
            if (m + 8 < M)
                *(float2*)&C[(size_t)(m + 8) * OUT_STRIDE + n] =
                    make_float2(acc[mt][nt][2], acc[mt][nt][3]);
        }
    }
}

// ---------------- SpMM: out[:,256:512] = segment_sum(val * ft[src]) ---------
__global__ __launch_bounds__(256)
void spmm_kernel(const float4* __restrict__ ft, float* __restrict__ out,
                 int Nn, int E) {
    int node = blockIdx.x * 4 + (threadIdx.x >> 6);
    int lane = threadIdx.x & 63;
    if (node >= Nn) return;

    int beg = g_off[node];
    int end = g_off[node + 1];
    if (beg < 0) beg = 0;
    if (end > E) end = E;
    if (end < beg) end = beg;

    float4 acc = make_float4(0.f, 0.f, 0.f, 0.f);
    int i = beg;
    for (; i + 4 <= end; i += 4) {
        uint2 e0 = g_csr[i + 0];
        uint2 e1 = g_csr[i + 1];
        uint2 e2 = g_csr[i + 2];
        uint2 e3 = g_csr[i + 3];
        float4 v0 = __ldg(&ft[(size_t)e0.x * 128 + lane]);
        float4 v1 = __ldg(&ft[(size_t)e1.x * 128 + lane]);
        float4 v2 = __ldg(&ft[(size_t)e2.x * 128 + lane]);
        float4 v3 = __ldg(&ft[(size_t)e3.x * 128 + lane]);
        float w0 = __uint_as_float(e0.y);
        float w1 = __uint_as_float(e1.y);
        float w2 = __uint_as_float(e2.y);
        float w3 = __uint_as_float(e3.y);
        acc.x += w0 * v0.x; acc.y += w0 * v0.y; acc.z += w0 * v0.z; acc.w += w0 * v0.w;
        acc.x += w1 * v1.x; acc.y += w1 * v1.y; acc.z += w1 * v1.z; acc.w += w1 * v1.w;
        acc.x += w2 * v2.x; acc.y += w2 * v2.y; acc.z += w2 * v2.z; acc.w += w2 * v2.w;
        acc.x += w3 * v3.x; acc.y += w3 * v3.y; acc.z += w3 * v3.z; acc.w += w3 * v3.w;
    }
    for (; i < end; i++) {
        uint2 e = g_csr[i];
        float4 v = __ldg(&ft[(size_t)e.x * 128 + lane]);
        float w = __uint_as_float(e.y);
        acc.x += w * v.x; acc.y += w * v.y; acc.z += w * v.z; acc.w += w * v.w;
    }

    ((float4*)out)[(size_t)node * 128 + 64 + lane] = acc;   // right half
}

// ---------------- launch ----------------------------------------------------
extern "C" void kernel_launch(void* const* d_in, const int* in_sizes, int n_in,
                              void* d_out, int out_size) {
    const float* input  = (const float*)d_in[0];
    const int*   esrc   = (const int*)d_in[1];
    const int*   edst   = (const int*)d_in[2];
    const float* eval_  = (const float*)d_in[3];
    const float* weight = (const float*)d_in[4];
    float* out = (float*)d_out;

    int M = out_size / OUT_STRIDE;   // 100000
    int E = in_sizes[3];             // fp32 edge_val count (unambiguous)
    int nb = (M + SCAN_BLK - 1) / SCAN_BLK;   // 98 scan blocks

    detect_kernel<<<1, 256>>>(esrc, edst, E);
    zero_cnt_kernel<<<(M + 255) / 256, 256>>>(M);
    hist_kernel<<<(E + 255) / 256, 256>>>(edst, E);
    scan_reduce_kernel<<<nb, SCAN_BLK>>>(M);
    scan_tops_kernel<<<1, 128>>>(nb, M);
    scan_apply_kernel<<<nb, SCAN_BLK>>>(M);
    scatter_kernel<<<(E + 255) / 256, 256>>>(esrc, edst, eval_, E);

    dim3 ggrid((M + 127) / 128, OUT_F / 128);
    gemm_tf32_kernel<<<ggrid, 256>>>(input, weight, out, M);

    spmm_kernel<<<(M + 3) / 4, 256>>>((const float4*)out, out, M, E);
}

// round 8
// speedup vs baseline: 1.8222x; 1.3396x over previous
#include <cuda_runtime.h>
#include <cuda_fp16.h>
#include <cstdint>

#define NODES 100000
#define IN_F 256
#define OUT_F 256
#define OUT_STRIDE 512
#define MAX_E 3200000
#define SCAN_BLK 1024
#define MAX_SCAN_BLOCKS 128

// ---------------- static device scratch (no runtime allocation) -------------
__device__ int     g_idx64;
__device__ int     g_cnt[NODES];
__device__ int     g_off[NODES + 1];
__device__ int     g_cursor[NODES];
__device__ int     g_bsum[MAX_SCAN_BLOCKS];
__device__ uint2   g_csr[MAX_E];
__device__ __half2 g_ft16[(size_t)NODES * 128];   // fp16 copy of ft, 51.2 MB

// ---------------- dtype probe (int64 edge indices -> odd words all zero) ----
__global__ void detect_kernel(const int* __restrict__ a,
                              const int* __restrict__ b, int E) {
    __shared__ int nz;
    if (threadIdx.x == 0) nz = 0;
    __syncthreads();
    int K = E < 2048 ? E : 2048;
    for (int i = threadIdx.x; i < K; i += blockDim.x) {
        if ((a[2 * i + 1] | b[2 * i + 1]) != 0) nz = 1;
    }
    __syncthreads();
    if (threadIdx.x == 0) g_idx64 = (nz == 0) ? 1 : 0;
}

// ---------------- CSR build -------------------------------------------------
__global__ void zero_cnt_kernel(int Nn) {
    int i = blockIdx.x * blockDim.x + threadIdx.x;
    if (i < Nn) g_cnt[i] = 0;
}

__global__ void hist_kernel(const int* __restrict__ dst, int E) {
    int stride = g_idx64 ? 2 : 1;
    int e = blockIdx.x * blockDim.x + threadIdx.x;
    if (e < E) {
        int d = dst[e * stride];
        if ((unsigned)d < (unsigned)NODES) atomicAdd(&g_cnt[d], 1);
    }
}

__global__ __launch_bounds__(SCAN_BLK)
void scan_reduce_kernel(int Nn) {
    __shared__ int red[32];
    int lane = threadIdx.x & 31;
    int wid  = threadIdx.x >> 5;
    int idx  = blockIdx.x * SCAN_BLK + threadIdx.x;
    int x = (idx < Nn) ? g_cnt[idx] : 0;
    #pragma unroll
    for (int d = 16; d > 0; d >>= 1) x += __shfl_down_sync(0xffffffffu, x, d);
    if (lane == 0) red[wid] = x;
    __syncthreads();
    if (wid == 0) {
        int s = red[lane];
        #pragma unroll
        for (int d = 16; d > 0; d >>= 1) s += __shfl_down_sync(0xffffffffu, s, d);
        if (lane == 0) g_bsum[blockIdx.x] = s;
    }
}

__global__ void scan_tops_kernel(int nb, int Nn) {
    __shared__ int wsum[4];
    int tid  = threadIdx.x;
    int lane = tid & 31;
    int wid  = tid >> 5;
    int x = (tid < nb) ? g_bsum[tid] : 0;
    int v = x;
    #pragma unroll
    for (int d = 1; d < 32; d <<= 1) {
        int t = __shfl_up_sync(0xffffffffu, v, d);
        if (lane >= d) v += t;
    }
    if (lane == 31) wsum[wid] = v;
    __syncthreads();
    int base = 0;
    #pragma unroll
    for (int w = 0; w < 4; w++) if (w < wid) base += wsum[w];
    if (tid < nb) g_bsum[tid] = base + v - x;
    if (tid == 127) g_off[Nn] = base + v;
}

__global__ __launch_bounds__(SCAN_BLK)
void scan_apply_kernel(int Nn) {
    __shared__ int wsum[32];
    int lane = threadIdx.x & 31;
    int wid  = threadIdx.x >> 5;
    int idx  = blockIdx.x * SCAN_BLK + threadIdx.x;
    int x = (idx < Nn) ? g_cnt[idx] : 0;
    int v = x;
    #pragma unroll
    for (int d = 1; d < 32; d <<= 1) {
        int t = __shfl_up_sync(0xffffffffu, v, d);
        if (lane >= d) v += t;
    }
    if (lane == 31) wsum[wid] = v;
    __syncthreads();
    if (wid == 0) {
        int s = wsum[lane];
        #pragma unroll
        for (int d = 1; d < 32; d <<= 1) {
            int t = __shfl_up_sync(0xffffffffu, s, d);
            if (lane >= d) s += t;
        }
        wsum[lane] = s;
    }
    __syncthreads();
    int base = g_bsum[blockIdx.x] + (wid ? wsum[wid - 1] : 0);
    int excl = base + v - x;
    if (idx < Nn) { g_off[idx] = excl; g_cursor[idx] = excl; }
}

__global__ void scatter_kernel(const int* __restrict__ src,
                               const int* __restrict__ dst,
                               const float* __restrict__ val, int E) {
    int stride = g_idx64 ? 2 : 1;
    int e = blockIdx.x * blockDim.x + threadIdx.x;
    if (e >= E) return;
    int d = dst[e * stride];
    if ((unsigned)d >= (unsigned)NODES) return;
    int slot = atomicAdd(&g_cursor[d], 1);
    if ((unsigned)slot < (unsigned)MAX_E)
        g_csr[slot] = make_uint2((unsigned)src[e * stride],
                                 __float_as_uint(val[e]));
}

// ---------------- tf32 tensor-core GEMM: out[:, 0:256] = input @ W ----------
// Also writes a fp16 copy of the result into g_ft16 for the SpMM gather.
#define AS_K 36

__device__ __forceinline__ uint32_t f2tf32(float f) {
    uint32_t u;
    asm("cvt.rna.tf32.f32 %0, %1;" : "=r"(u) : "f"(f));
    return u;
}

__device__ __forceinline__ void mma_tf32(float& c0, float& c1, float& c2, float& c3,
                                         uint32_t a0, uint32_t a1, uint32_t a2, uint32_t a3,
                                         uint32_t b0, uint32_t b1) {
    asm volatile(
        "mma.sync.aligned.m16n8k8.row.col.f32.tf32.tf32.f32 "
        "{%0,%1,%2,%3}, {%4,%5,%6,%7}, {%8,%9}, {%0,%1,%2,%3};\n"
        : "+f"(c0), "+f"(c1), "+f"(c2), "+f"(c3)
        : "r"(a0), "r"(a1), "r"(a2), "r"(a3), "r"(b0), "r"(b1));
}

__global__ __launch_bounds__(256, 2)
void gemm_tf32_kernel(const float* __restrict__ A,
                      const float* __restrict__ W,
                      float* __restrict__ C,
                      int M) {
    __shared__ uint32_t As[128 * AS_K];
    __shared__ uint32_t Bs[128 * AS_K];

    int tid  = threadIdx.x;
    int lane = tid & 31;
    int warp = tid >> 5;
    int wm = (warp & 3) * 32;
    int wn = (warp >> 2) * 64;
    int g = lane >> 2;
    int t = lane & 3;

    int row0 = blockIdx.x * 128;
    int n0   = blockIdx.y * 128;

    float acc[2][8][4];
    #pragma unroll
    for (int mt = 0; mt < 2; mt++)
        #pragma unroll
        for (int nt = 0; nt < 8; nt++)
            #pragma unroll
            for (int c = 0; c < 4; c++) acc[mt][nt][c] = 0.f;

    for (int k0 = 0; k0 < IN_F; k0 += 32) {
        #pragma unroll
        for (int p = 0; p < 4; p++) {
            int idx = tid + 256 * p;
            int r  = idx >> 3;
            int c4 = idx & 7;
            int grow = row0 + r;
            float4 v = make_float4(0.f, 0.f, 0.f, 0.f);
            if (grow < M) v = *(const float4*)&A[(size_t)grow * IN_F + k0 + c4 * 4];
            uint32_t* d = &As[r * AS_K + c4 * 4];
            d[0] = f2tf32(v.x); d[1] = f2tf32(v.y);
            d[2] = f2tf32(v.z); d[3] = f2tf32(v.w);
        }
        #pragma unroll
        for (int p = 0; p < 4; p++) {
            int idx = tid + 256 * p;
            int k  = idx >> 5;
            int c4 = idx & 31;
            float4 v = *(const float4*)&W[(size_t)(k0 + k) * OUT_F + n0 + c4 * 4];
            Bs[(c4 * 4 + 0) * AS_K + k] = f2tf32(v.x);
            Bs[(c4 * 4 + 1) * AS_K + k] = f2tf32(v.y);
            Bs[(c4 * 4 + 2) * AS_K + k] = f2tf32(v.z);
            Bs[(c4 * 4 + 3) * AS_K + k] = f2tf32(v.w);
        }
        __syncthreads();

        #pragma unroll
        for (int ks = 0; ks < 32; ks += 8) {
            uint32_t af[2][4];
            #pragma unroll
            for (int mt = 0; mt < 2; mt++) {
                int m = wm + mt * 16 + g;
                af[mt][0] = As[m * AS_K + ks + t];
                af[mt][1] = As[(m + 8) * AS_K + ks + t];
                af[mt][2] = As[m * AS_K + ks + t + 4];
                af[mt][3] = As[(m + 8) * AS_K + ks + t + 4];
            }
            #pragma unroll
            for (int nt = 0; nt < 8; nt++) {
                int n = wn + nt * 8 + g;
                uint32_t b0 = Bs[n * AS_K + ks + t];
                uint32_t b1 = Bs[n * AS_K + ks + t + 4];
                #pragma unroll
                for (int mt = 0; mt < 2; mt++)
                    mma_tf32(acc[mt][nt][0], acc[mt][nt][1],
                             acc[mt][nt][2], acc[mt][nt][3],
                             af[mt][0], af[mt][1], af[mt][2], af[mt][3], b0, b1);
            }
        }
        __syncthreads();
    }

    #pragma unroll
    for (int mt = 0; mt < 2; mt++) {
        #pragma unroll
        for (int nt = 0; nt < 8; nt++) {
            int m = row0 + wm + mt * 16 + g;
            int n = n0 + wn + nt * 8 + 2 * t;       // even
            if (m < M) {
                *(float2*)&C[(size_t)m * OUT_STRIDE + n] =
                    make_float2(acc[mt][nt][0], acc[mt][nt][1]);
                g_ft16[(size_t)m * 128 + (n >> 1)] =
                    __floats2half2_rn(acc[mt][nt][0], acc[mt][nt][1]);
            }
            if (m + 8 < M) {
                *(float2*)&C[(size_t)(m + 8) * OUT_STRIDE + n] =
                    make_float2(acc[mt][nt][2], acc[mt][nt][3]);
                g_ft16[(size_t)(m + 8) * 128 + (n >> 1)] =
                    __floats2half2_rn(acc[mt][nt][2], acc[mt][nt][3]);
            }
        }
    }
}

// ---------------- SpMM: out[:,256:512] = segment_sum(val * ft16[src]) -------
// 1 warp per dst node, 8 nodes per 256-thread block.
// Each lane owns 8 features: one uint4 (= 4 half2 = 16B) per edge, coalesced.

__device__ __forceinline__ void acc_edge(float2* a, uint4 v, float wgt) {
    float2 f;
    f = __half22float2(*(const __half2*)&v.x);
    a[0].x += wgt * f.x; a[0].y += wgt * f.y;
    f = __half22float2(*(const __half2*)&v.y);
    a[1].x += wgt * f.x; a[1].y += wgt * f.y;
    f = __half22float2(*(const __half2*)&v.z);
    a[2].x += wgt * f.x; a[2].y += wgt * f.y;
    f = __half22float2(*(const __half2*)&v.w);
    a[3].x += wgt * f.x; a[3].y += wgt * f.y;
}

__global__ __launch_bounds__(256)
void spmm_kernel(float* __restrict__ out, int Nn, int E) {
    int node = blockIdx.x * 8 + (threadIdx.x >> 5);
    int lane = threadIdx.x & 31;
    if (node >= Nn) return;

    int beg = g_off[node];
    int end = g_off[node + 1];
    if (beg < 0) beg = 0;
    if (end > E) end = E;
    if (end < beg) end = beg;

    const uint4* ftv = (const uint4*)g_ft16;   // 32 uint4 per row

    float2 a[4];
    a[0] = make_float2(0.f, 0.f); a[1] = a[0]; a[2] = a[0]; a[3] = a[0];

    int i = beg;
    for (; i + 4 <= end; i += 4) {
        uint2 e0 = g_csr[i + 0];
        uint2 e1 = g_csr[i + 1];
        uint2 e2 = g_csr[i + 2];
        uint2 e3 = g_csr[i + 3];
        uint4 v0 = __ldg(&ftv[(size_t)e0.x * 32 + lane]);
        uint4 v1 = __ldg(&ftv[(size_t)e1.x * 32 + lane]);
        uint4 v2 = __ldg(&ftv[(size_t)e2.x * 32 + lane]);
        uint4 v3 = __ldg(&ftv[(size_t)e3.x * 32 + lane]);
        acc_edge(a, v0, __uint_as_float(e0.y));
        acc_edge(a, v1, __uint_as_float(e1.y));
        acc_edge(a, v2, __uint_as_float(e2.y));
        acc_edge(a, v3, __uint_as_float(e3.y));
    }
    for (; i < end; i++) {
        uint2 e = g_csr[i];
        uint4 v = __ldg(&ftv[(size_t)e.x * 32 + lane]);
        acc_edge(a, v, __uint_as_float(e.y));
    }

    // features 8*lane .. 8*lane+7 of the right half
    float* dst = &out[(size_t)node * OUT_STRIDE + OUT_F + lane * 8];
    *(float4*)dst       = make_float4(a[0].x, a[0].y, a[1].x, a[1].y);
    *(float4*)(dst + 4) = make_float4(a[2].x, a[2].y, a[3].x, a[3].y);
}

// ---------------- launch ----------------------------------------------------
extern "C" void kernel_launch(void* const* d_in, const int* in_sizes, int n_in,
                              void* d_out, int out_size) {
    const float* input  = (const float*)d_in[0];
    const int*   esrc   = (const int*)d_in[1];
    const int*   edst   = (const int*)d_in[2];
    const float* eval_  = (const float*)d_in[3];
    const float* weight = (const float*)d_in[4];
    float* out = (float*)d_out;

    int M = out_size / OUT_STRIDE;
    int E = in_sizes[3];
    int nb = (M + SCAN_BLK - 1) / SCAN_BLK;

    detect_kernel<<<1, 256>>>(esrc, edst, E);
    zero_cnt_kernel<<<(M + 255) / 256, 256>>>(M);
    hist_kernel<<<(E + 255) / 256, 256>>>(edst, E);
    scan_reduce_kernel<<<nb, SCAN_BLK>>>(M);
    scan_tops_kernel<<<1, 128>>>(nb, M);
    scan_apply_kernel<<<nb, SCAN_BLK>>>(M);
    scatter_kernel<<<(E + 255) / 256, 256>>>(esrc, edst, eval_, E);

    dim3 ggrid((M + 127) / 128, OUT_F / 128);
    gemm_tf32_kernel<<<ggrid, 256>>>(input, weight, out, M);

    spmm_kernel<<<(M + 7) / 8, 256>>>(out, M, E);
}

// round 9
// speedup vs baseline: 1.8702x; 1.0263x over previous
#include <cuda_runtime.h>
#include <cuda_fp16.h>
#include <cstdint>

#define NODES 100000
#define IN_F 256
#define OUT_F 256
#define OUT_STRIDE 512
#define MAX_E 3200000
#define SCAN_BLK 1024
#define MAX_SCAN_BLOCKS 128
#define HIST_BLOCKS 1024

// ---------------- static device scratch (no runtime allocation) -------------
__device__ int     g_idx64;
__device__ int     g_cnt[NODES];
__device__ int     g_off[NODES + 1];
__device__ int     g_cursor[NODES];
__device__ int     g_bsum[MAX_SCAN_BLOCKS];
__device__ uint2   g_csr[MAX_E];
__device__ __half2 g_ft16[(size_t)NODES * 128];   // fp16 copy of ft, 51.2 MB

// ---------------- dtype probe (int64 edge indices -> odd words all zero) ----
__global__ void detect_kernel(const int* __restrict__ a,
                              const int* __restrict__ b, int E) {
    __shared__ int nz;
    if (threadIdx.x == 0) nz = 0;
    __syncthreads();
    int K = E < 2048 ? E : 2048;
    for (int i = threadIdx.x; i < K; i += blockDim.x) {
        if ((a[2 * i + 1] | b[2 * i + 1]) != 0) nz = 1;
    }
    __syncthreads();
    if (threadIdx.x == 0) g_idx64 = (nz == 0) ? 1 : 0;
}

__global__ void zero_cnt_kernel(int Nn) {
    int i = blockIdx.x * blockDim.x + threadIdx.x;
    if (i < Nn) g_cnt[i] = 0;
}

// ---------------- scan ------------------------------------------------------
__global__ __launch_bounds__(SCAN_BLK)
void scan_reduce_kernel(int Nn) {
    __shared__ int red[32];
    int lane = threadIdx.x & 31;
    int wid  = threadIdx.x >> 5;
    int idx  = blockIdx.x * SCAN_BLK + threadIdx.x;
    int x = (idx < Nn) ? g_cnt[idx] : 0;
    #pragma unroll
    for (int d = 16; d > 0; d >>= 1) x += __shfl_down_sync(0xffffffffu, x, d);
    if (lane == 0) red[wid] = x;
    __syncthreads();
    if (wid == 0) {
        int s = red[lane];
        #pragma unroll
        for (int d = 16; d > 0; d >>= 1) s += __shfl_down_sync(0xffffffffu, s, d);
        if (lane == 0) g_bsum[blockIdx.x] = s;
    }
}

__global__ void scan_tops_kernel(int nb, int Nn) {
    __shared__ int wsum[4];
    int tid  = threadIdx.x;
    int lane = tid & 31;
    int wid  = tid >> 5;
    int x = (tid < nb) ? g_bsum[tid] : 0;
    int v = x;
    #pragma unroll
    for (int d = 1; d < 32; d <<= 1) {
        int t = __shfl_up_sync(0xffffffffu, v, d);
        if (lane >= d) v += t;
    }
    if (lane == 31) wsum[wid] = v;
    __syncthreads();
    int base = 0;
    #pragma unroll
    for (int w = 0; w < 4; w++) if (w < wid) base += wsum[w];
    if (tid < nb) g_bsum[tid] = base + v - x;
    if (tid == 127) g_off[Nn] = base + v;
}

__global__ __launch_bounds__(SCAN_BLK)
void scan_apply_kernel(int Nn) {
    __shared__ int wsum[32];
    int lane = threadIdx.x & 31;
    int wid  = threadIdx.x >> 5;
    int idx  = blockIdx.x * SCAN_BLK + threadIdx.x;
    int x = (idx < Nn) ? g_cnt[idx] : 0;
    int v = x;
    #pragma unroll
    for (int d = 1; d < 32; d <<= 1) {
        int t = __shfl_up_sync(0xffffffffu, v, d);
        if (lane >= d) v += t;
    }
    if (lane == 31) wsum[wid] = v;
    __syncthreads();
    if (wid == 0) {
        int s = wsum[lane];
        #pragma unroll
        for (int d = 1; d < 32; d <<= 1) {
            int t = __shfl_up_sync(0xffffffffu, s, d);
            if (lane >= d) s += t;
        }
        wsum[lane] = s;
    }
    __syncthreads();
    int base = g_bsum[blockIdx.x] + (wid ? wsum[wid - 1] : 0);
    int excl = base + v - x;
    if (idx < Nn) { g_off[idx] = excl; g_cursor[idx] = excl; }
}

__global__ void scatter_kernel(const int* __restrict__ src,
                               const int* __restrict__ dst,
                               const float* __restrict__ val, int E) {
    int stride = g_idx64 ? 2 : 1;
    int e = blockIdx.x * blockDim.x + threadIdx.x;
    if (e >= E) return;
    int d = dst[e * stride];
    if ((unsigned)d >= (unsigned)NODES) return;
    int slot = atomicAdd(&g_cursor[d], 1);
    if ((unsigned)slot < (unsigned)MAX_E)
        g_csr[slot] = make_uint2((unsigned)src[e * stride],
                                 __float_as_uint(val[e]));
}

// ---------------- fused GEMM (A-prefetch) + edge histogram ------------------
#define AS_K 36

__device__ __forceinline__ uint32_t f2tf32(float f) {
    uint32_t u;
    asm("cvt.rna.tf32.f32 %0, %1;" : "=r"(u) : "f"(f));
    return u;
}

__device__ __forceinline__ void mma_tf32(float& c0, float& c1, float& c2, float& c3,
                                         uint32_t a0, uint32_t a1, uint32_t a2, uint32_t a3,
                                         uint32_t b0, uint32_t b1) {
    asm volatile(
        "mma.sync.aligned.m16n8k8.row.col.f32.tf32.tf32.f32 "
        "{%0,%1,%2,%3}, {%4,%5,%6,%7}, {%8,%9}, {%0,%1,%2,%3};\n"
        : "+f"(c0), "+f"(c1), "+f"(c2), "+f"(c3)
        : "r"(a0), "r"(a1), "r"(a2), "r"(a3), "r"(b0), "r"(b1));
}

__global__ __launch_bounds__(256)
void gemm_hist_kernel(const float* __restrict__ A,
                      const float* __restrict__ W,
                      const int* __restrict__ edst,
                      float* __restrict__ C,
                      int M, int E, int nGemm) {
    // ---------- histogram blocks ----------
    if ((int)blockIdx.x >= nGemm) {
        int stride = g_idx64 ? 2 : 1;
        int nh = gridDim.x - nGemm;
        int tid0 = (blockIdx.x - nGemm) * 256 + threadIdx.x;
        for (int e = tid0; e < E; e += nh * 256) {
            int d = edst[e * stride];
            if ((unsigned)d < (unsigned)NODES) atomicAdd(&g_cnt[d], 1);
        }
        return;
    }

    // ---------- GEMM blocks ----------
    __shared__ uint32_t As[128 * AS_K];
    __shared__ uint32_t Bs[128 * AS_K];

    int tid  = threadIdx.x;
    int lane = tid & 31;
    int warp = tid >> 5;
    int wm = (warp & 3) * 32;
    int wn = (warp >> 2) * 64;
    int g = lane >> 2;
    int t = lane & 3;

    int row0 = (blockIdx.x >> 1) * 128;
    int n0   = (blockIdx.x & 1) * 128;

    // A-load lane mapping (same every iteration)
    int a_r[4], a_c4[4];
    #pragma unroll
    for (int p = 0; p < 4; p++) {
        int idx = tid + 256 * p;
        a_r[p]  = idx >> 3;
        a_c4[p] = idx & 7;
    }

    float acc[2][8][4];
    #pragma unroll
    for (int mt = 0; mt < 2; mt++)
        #pragma unroll
        for (int nt = 0; nt < 8; nt++)
            #pragma unroll
            for (int c = 0; c < 4; c++) acc[mt][nt][c] = 0.f;

    // prefetch A tile for k0 = 0
    float4 pa[4];
    #pragma unroll
    for (int p = 0; p < 4; p++) {
        int grow = row0 + a_r[p];
        pa[p] = make_float4(0.f, 0.f, 0.f, 0.f);
        if (grow < M) pa[p] = *(const float4*)&A[(size_t)grow * IN_F + a_c4[p] * 4];
    }

    for (int k0 = 0; k0 < IN_F; k0 += 32) {
        // store prefetched A tile (cvt to tf32)
        #pragma unroll
        for (int p = 0; p < 4; p++) {
            uint32_t* d = &As[a_r[p] * AS_K + a_c4[p] * 4];
            d[0] = f2tf32(pa[p].x); d[1] = f2tf32(pa[p].y);
            d[2] = f2tf32(pa[p].z); d[3] = f2tf32(pa[p].w);
        }
        // B tile (L2-resident, load directly)
        #pragma unroll
        for (int p = 0; p < 4; p++) {
            int idx = tid + 256 * p;
            int k  = idx >> 5;
            int c4 = idx & 31;
            float4 v = *(const float4*)&W[(size_t)(k0 + k) * OUT_F + n0 + c4 * 4];
            Bs[(c4 * 4 + 0) * AS_K + k] = f2tf32(v.x);
            Bs[(c4 * 4 + 1) * AS_K + k] = f2tf32(v.y);
            Bs[(c4 * 4 + 2) * AS_K + k] = f2tf32(v.z);
            Bs[(c4 * 4 + 3) * AS_K + k] = f2tf32(v.w);
        }
        __syncthreads();

        // prefetch next A tile while computing this one
        if (k0 + 32 < IN_F) {
            #pragma unroll
            for (int p = 0; p < 4; p++) {
                int grow = row0 + a_r[p];
                float4 v = make_float4(0.f, 0.f, 0.f, 0.f);
                if (grow < M)
                    v = *(const float4*)&A[(size_t)grow * IN_F + (k0 + 32) + a_c4[p] * 4];
                pa[p] = v;
            }
        }

        #pragma unroll
        for (int ks = 0; ks < 32; ks += 8) {
            uint32_t af[2][4];
            #pragma unroll
            for (int mt = 0; mt < 2; mt++) {
                int m = wm + mt * 16 + g;
                af[mt][0] = As[m * AS_K + ks + t];
                af[mt][1] = As[(m + 8) * AS_K + ks + t];
                af[mt][2] = As[m * AS_K + ks + t + 4];
                af[mt][3] = As[(m + 8) * AS_K + ks + t + 4];
            }
            #pragma unroll
            for (int nt = 0; nt < 8; nt++) {
                int n = wn + nt * 8 + g;
                uint32_t b0 = Bs[n * AS_K + ks + t];
                uint32_t b1 = Bs[n * AS_K + ks + t + 4];
                #pragma unroll
                for (int mt = 0; mt < 2; mt++)
                    mma_tf32(acc[mt][nt][0], acc[mt][nt][1],
                             acc[mt][nt][2], acc[mt][nt][3],
                             af[mt][0], af[mt][1], af[mt][2], af[mt][3], b0, b1);
            }
        }
        __syncthreads();
    }

    #pragma unroll
    for (int mt = 0; mt < 2; mt++) {
        #pragma unroll
        for (int nt = 0; nt < 8; nt++) {
            int m = row0 + wm + mt * 16 + g;
            int n = n0 + wn + nt * 8 + 2 * t;
            if (m < M) {
                *(float2*)&C[(size_t)m * OUT_STRIDE + n] =
                    make_float2(acc[mt][nt][0], acc[mt][nt][1]);
                g_ft16[(size_t)m * 128 + (n >> 1)] =
                    __floats2half2_rn(acc[mt][nt][0], acc[mt][nt][1]);
            }
            if (m + 8 < M) {
                *(float2*)&C[(size_t)(m + 8) * OUT_STRIDE + n] =
                    make_float2(acc[mt][nt][2], acc[mt][nt][3]);
                g_ft16[(size_t)(m + 8) * 128 + (n >> 1)] =
                    __floats2half2_rn(acc[mt][nt][2], acc[mt][nt][3]);
            }
        }
    }
}

// ---------------- SpMM: out[:,256:512] = segment_sum(val * ft16[src]) -------
__device__ __forceinline__ void acc_edge(float2* a, uint4 v, float wgt) {
    float2 f;
    f = __half22float2(*(const __half2*)&v.x);
    a[0].x += wgt * f.x; a[0].y += wgt * f.y;
    f = __half22float2(*(const __half2*)&v.y);
    a[1].x += wgt * f.x; a[1].y += wgt * f.y;
    f = __half22float2(*(const __half2*)&v.z);
    a[2].x += wgt * f.x; a[2].y += wgt * f.y;
    f = __half22float2(*(const __half2*)&v.w);
    a[3].x += wgt * f.x; a[3].y += wgt * f.y;
}

__global__ __launch_bounds__(256)
void spmm_kernel(float* __restrict__ out, int Nn, int E) {
    int node = blockIdx.x * 8 + (threadIdx.x >> 5);
    int lane = threadIdx.x & 31;
    if (node >= Nn) return;

    int beg = g_off[node];
    int end = g_off[node + 1];
    if (beg < 0) beg = 0;
    if (end > E) end = E;
    if (end < beg) end = beg;

    const uint4* ftv = (const uint4*)g_ft16;

    float2 a[4];
    a[0] = make_float2(0.f, 0.f); a[1] = a[0]; a[2] = a[0]; a[3] = a[0];

    int i = beg;
    for (; i + 4 <= end; i += 4) {
        uint2 e0 = g_csr[i + 0];
        uint2 e1 = g_csr[i + 1];
        uint2 e2 = g_csr[i + 2];
        uint2 e3 = g_csr[i + 3];
        uint4 v0 = __ldg(&ftv[(size_t)e0.x * 32 + lane]);
        uint4 v1 = __ldg(&ftv[(size_t)e1.x * 32 + lane]);
        uint4 v2 = __ldg(&ftv[(size_t)e2.x * 32 + lane]);
        uint4 v3 = __ldg(&ftv[(size_t)e3.x * 32 + lane]);
        acc_edge(a, v0, __uint_as_float(e0.y));
        acc_edge(a, v1, __uint_as_float(e1.y));
        acc_edge(a, v2, __uint_as_float(e2.y));
        acc_edge(a, v3, __uint_as_float(e3.y));
    }
    for (; i < end; i++) {
        uint2 e = g_csr[i];
        uint4 v = __ldg(&ftv[(size_t)e.x * 32 + lane]);
        acc_edge(a, v, __uint_as_float(e.y));
    }

    float* dst = &out[(size_t)node * OUT_STRIDE + OUT_F + lane * 8];
    *(float4*)dst       = make_float4(a[0].x, a[0].y, a[1].x, a[1].y);
    *(float4*)(dst + 4) = make_float4(a[2].x, a[2].y, a[3].x, a[3].y);
}

// ---------------- launch ----------------------------------------------------
extern "C" void kernel_launch(void* const* d_in, const int* in_sizes, int n_in,
                              void* d_out, int out_size) {
    const float* input  = (const float*)d_in[0];
    const int*   esrc   = (const int*)d_in[1];
    const int*   edst   = (const int*)d_in[2];
    const float* eval_  = (const float*)d_in[3];
    const float* weight = (const float*)d_in[4];
    float* out = (float*)d_out;

    int M = out_size / OUT_STRIDE;
    int E = in_sizes[3];
    int nb = (M + SCAN_BLK - 1) / SCAN_BLK;
    int nGemm = ((M + 127) / 128) * 2;

    detect_kernel<<<1, 256>>>(esrc, edst, E);
    zero_cnt_kernel<<<(M + 255) / 256, 256>>>(M);

    gemm_hist_kernel<<<nGemm + HIST_BLOCKS, 256>>>(input, weight, edst, out,
                                                   M, E, nGemm);

    scan_reduce_kernel<<<nb, SCAN_BLK>>>(M);
    scan_tops_kernel<<<1, 128>>>(nb, M);
    scan_apply_kernel<<<nb, SCAN_BLK>>>(M);
    scatter_kernel<<<(E + 255) / 256, 256>>>(esrc, edst, eval_, E);

    spmm_kernel<<<(M + 7) / 8, 256>>>(out, M, E);
}